// round 5
// baseline (speedup 1.0000x reference)
#include <cuda_runtime.h>
#include <math.h>

// Problem constants
#define B 32
#define L 4096
#define H 1024
#define GCHUNKS 32
#define NYBLK (L / 32)      // 128 energy blocks per b

// Scratch (device globals — no allocation allowed)
__device__ float  g_vpart[GCHUNKS][B * H];  // 4 MB partials for v = hid @ W
__device__ float  g_v[B * H];               // 128 KB
__device__ float  g_energies[B * L];        // 512 KB
__device__ float2 g_stats[B * NYBLK];       // per-block (max, sumexp)

// ---------------------------------------------------------------------------
// Kernel 1: partial v[b,h] = sum_{g in chunk} hid[b,g] * W[g,h]
// grid = (H/256, GCHUNKS, B/8), block = 256. Thread owns one h for 8 b's.
// ---------------------------------------------------------------------------
__global__ void k_vpart(const float* __restrict__ hid, const float* __restrict__ W)
{
    __shared__ float sh[8][32];  // hid tile [b][gi], 1 KB
    const int h  = blockIdx.x * 256 + threadIdx.x;
    const int g0 = blockIdx.y * 32;
    const int b0 = blockIdx.z * 8;

    if (threadIdx.x < 256) {
        int b = threadIdx.x >> 5, gi = threadIdx.x & 31;
        sh[b][gi] = hid[(b0 + b) * H + g0 + gi];
    }
    __syncthreads();

    float acc[8];
#pragma unroll
    for (int b = 0; b < 8; b++) acc[b] = 0.f;

#pragma unroll
    for (int gi = 0; gi < 32; gi += 4) {
        const float w0 = W[(size_t)(g0 + gi + 0) * H + h];
        const float w1 = W[(size_t)(g0 + gi + 1) * H + h];
        const float w2 = W[(size_t)(g0 + gi + 2) * H + h];
        const float w3 = W[(size_t)(g0 + gi + 3) * H + h];
#pragma unroll
        for (int b = 0; b < 8; b++) {
            float4 hv = *reinterpret_cast<const float4*>(&sh[b][gi]);
            acc[b] = fmaf(hv.x, w0, acc[b]);
            acc[b] = fmaf(hv.y, w1, acc[b]);
            acc[b] = fmaf(hv.z, w2, acc[b]);
            acc[b] = fmaf(hv.w, w3, acc[b]);
        }
    }
#pragma unroll
    for (int b = 0; b < 8; b++)
        g_vpart[blockIdx.y][(size_t)(b0 + b) * H + h] = acc[b];
}

// ---------------------------------------------------------------------------
// Kernel 2: deterministic reduce of partials
// ---------------------------------------------------------------------------
__global__ void k_vreduce()
{
    const int i = blockIdx.x * blockDim.x + threadIdx.x;
    float s = 0.f;
#pragma unroll
    for (int gc = 0; gc < GCHUNKS; gc++) s += g_vpart[gc][i];
    g_v[i] = s;
}

// ---------------------------------------------------------------------------
// Kernel 3 (HBM-bound): energies[b,l] = v[b] . enc[l,b], + partial softmax
// stats. Block = 256 thr = 8 warps, one b, 32 l's (4 per warp). v[b] staged
// in smem once. Epilogue: block max + sumexp -> g_stats (deterministic
// butterfly reductions only).  grid = (B, L/32).
// ---------------------------------------------------------------------------
__global__ void k_energies(const float* __restrict__ enc)
{
    __shared__ float4 sv[H / 4];   // 4 KB
    __shared__ float  esm[32];
    const int b = blockIdx.x;

    sv[threadIdx.x] = reinterpret_cast<const float4*>(g_v + (size_t)b * H)[threadIdx.x];
    __syncthreads();

    const int w    = threadIdx.x >> 5;
    const int lane = threadIdx.x & 31;
    const int l0   = blockIdx.y * 32 + w * 4;

    float acc[4] = {0.f, 0.f, 0.f, 0.f};
#pragma unroll
    for (int j = 0; j < 4; j++) {
        const float4* e4 = reinterpret_cast<const float4*>(enc + ((size_t)(l0 + j) * B + b) * H);
#pragma unroll
        for (int i = 0; i < 8; i++) {
            float4 a = e4[lane + 32 * i];
            float4 v = sv[lane + 32 * i];
            acc[j] = fmaf(a.x, v.x, acc[j]);
            acc[j] = fmaf(a.y, v.y, acc[j]);
            acc[j] = fmaf(a.z, v.z, acc[j]);
            acc[j] = fmaf(a.w, v.w, acc[j]);
        }
    }
#pragma unroll
    for (int j = 0; j < 4; j++)
#pragma unroll
        for (int off = 16; off; off >>= 1)
            acc[j] += __shfl_xor_sync(0xFFFFFFFFu, acc[j], off);

    if (lane == 0) {
        float4 e4v = make_float4(acc[0], acc[1], acc[2], acc[3]);
        *reinterpret_cast<float4*>(&g_energies[(size_t)b * L + l0]) = e4v;
        *reinterpret_cast<float4*>(&esm[w * 4]) = e4v;
    }
    __syncthreads();

    if (w == 0) {
        float e = esm[lane];
        float m = e;
#pragma unroll
        for (int off = 16; off; off >>= 1)
            m = fmaxf(m, __shfl_xor_sync(0xFFFFFFFFu, m, off));
        float s = __expf(e - m);
#pragma unroll
        for (int off = 16; off; off >>= 1)
            s += __shfl_xor_sync(0xFFFFFFFFu, s, off);
        if (lane == 0)
            g_stats[b * NYBLK + blockIdx.y] = make_float2(m, s);
    }
}

// ---------------------------------------------------------------------------
// Kernel 4: combine stats + normalize. grid (B, 4), block 1024; each block
// recombines its b's 128 stats (deterministic) then writes 1024 outputs.
// (hid.bias term is constant over l -> cancels in softmax -> omitted.)
// ---------------------------------------------------------------------------
__global__ void k_norm(float* __restrict__ out)
{
    __shared__ float2 ssm[NYBLK];
    __shared__ float  sMS[2];
    const int b   = blockIdx.x;
    const int tid = threadIdx.x;

    if (tid < NYBLK) ssm[tid] = g_stats[b * NYBLK + tid];
    __syncthreads();

    if (tid < 32) {
        float2 st[4];
        float m = -INFINITY;
#pragma unroll
        for (int k = 0; k < 4; k++) {
            st[k] = ssm[tid * 4 + k];
            m = fmaxf(m, st[k].x);
        }
#pragma unroll
        for (int off = 16; off; off >>= 1)
            m = fmaxf(m, __shfl_xor_sync(0xFFFFFFFFu, m, off));
        float s = 0.f;
#pragma unroll
        for (int k = 0; k < 4; k++)
            s += st[k].y * __expf(st[k].x - m);
#pragma unroll
        for (int off = 16; off; off >>= 1)
            s += __shfl_xor_sync(0xFFFFFFFFu, s, off);
        if (tid == 0) { sMS[0] = m; sMS[1] = 1.f / s; }
    }
    __syncthreads();

    const float M = sMS[0], invS = sMS[1];
    const size_t idx = (size_t)b * L + blockIdx.y * 1024 + tid;
    out[idx] = __expf(g_energies[idx] - M) * invS;
}

// ---------------------------------------------------------------------------
// Launch. Inputs (metadata order): hidden [1,B,H], encoder_outputs [L,B,H],
// W [H,H], b [H]. Output: [B,1,L] float32.
// ---------------------------------------------------------------------------
extern "C" void kernel_launch(void* const* d_in, const int* in_sizes, int n_in,
                              void* d_out, int out_size)
{
    const float* hid = (const float*)d_in[0];
    const float* enc = (const float*)d_in[1];
    const float* W   = (const float*)d_in[2];
    // d_in[3] (bias) cancels in softmax -> unused.
    float* out = (float*)d_out;

    k_vpart<<<dim3(H / 256, GCHUNKS, B / 8), 256>>>(hid, W);
    k_vreduce<<<(B * H) / 256, 256>>>();
    k_energies<<<dim3(B, L / 32), 256>>>(enc);
    k_norm<<<dim3(B, 4), 1024>>>(out);
}